// round 1
// baseline (speedup 1.0000x reference)
#include <cuda_runtime.h>

#define NHEADS 5
#define BATCH  32
#define CH     512
#define HH     16
#define WW     16
#define NN     256      // HH*WW
#define CC5    2560     // 5*CH
#define KCONV  4608     // CH*9
#define BN_EPS 1e-5f

// ---------------- scratch (device globals; no allocation allowed) ----------------
__device__ float g_Q[(size_t)NHEADS * BATCH * CH * NN];
__device__ float g_K[(size_t)NHEADS * BATCH * CH * NN];   // K + rel-pos folded in
__device__ float g_V[(size_t)NHEADS * BATCH * CH * NN];
__device__ float g_E[(size_t)NHEADS * BATCH * NN * NN];   // energy -> attn (in place)
__device__ float g_O[(size_t)NHEADS * BATCH * CH * NN];   // per-head attention out
__device__ float g_WGT[BATCH * 4 * NN];                   // sigmoid(bn(msw)) weights
__device__ float g_MS[(size_t)BATCH * CH * NN];           // x_ms before conv
__device__ float g_CV[(size_t)BATCH * CH * NN];           // conv output

// =================================================================================
// Kernel 1: Q/K/V 1x1-conv GEMMs.  Per (mat, head, batch): [512x512] @ [512x256]
//   mat 0 = Q (+bias), mat 1 = K (+bias + rel-pos), mat 2 = V (+bias)
// =================================================================================
__global__ __launch_bounds__(256) void qkv_kernel(
    const float* __restrict__ x0, const float* __restrict__ x1,
    const float* __restrict__ x2, const float* __restrict__ x3,
    const float* __restrict__ x4,
    const float* __restrict__ qW, const float* __restrict__ qB,
    const float* __restrict__ kW, const float* __restrict__ kB,
    const float* __restrict__ vW, const float* __restrict__ vB,
    const float* __restrict__ relH, const float* __restrict__ relW)
{
    __shared__ float As[16][68];   // [k][row(o)]  (padded: aligned float4, few conflicts)
    __shared__ float Bs[16][68];   // [k][col(n)]

    int z   = blockIdx.z;
    int mat = z / (NHEADS * BATCH);
    int hb  = z % (NHEADS * BATCH);
    int hd  = hb / BATCH, b = hb % BATCH;

    const float* Wm; const float* bias; float* outbase;
    if (mat == 0)      { Wm = qW; bias = qB; outbase = g_Q; }
    else if (mat == 1) { Wm = kW; bias = kB; outbase = g_K; }
    else               { Wm = vW; bias = vB; outbase = g_V; }
    Wm  += (size_t)hd * CH * CH;
    bias += hd * CH;
    const float* X = (hd == 0 ? x0 : hd == 1 ? x1 : hd == 2 ? x2 : hd == 3 ? x3 : x4)
                     + (size_t)b * CH * NN;
    float* Out = outbase + (size_t)(hd * BATCH + b) * CH * NN;

    int n0 = blockIdx.x * 64, m0 = blockIdx.y * 64;
    int tid = threadIdx.x;
    int tx = tid & 15, ty = tid >> 4;

    float acc[4][4] = {};

    for (int k0 = 0; k0 < CH; k0 += 16) {
        {   // A: 64(o) x 16(c), W row-major [o][c]
            int c = tid & 15, o = tid >> 4;
            #pragma unroll
            for (int r = 0; r < 4; r++)
                As[c][o + r * 16] = Wm[(size_t)(m0 + o + r * 16) * CH + k0 + c];
        }
        {   // B: 16(c) x 64(n), X [c][n]
            int nn = tid & 63, cc = tid >> 6;
            #pragma unroll
            for (int r = 0; r < 4; r++)
                Bs[cc + r * 4][nn] = X[(size_t)(k0 + cc + r * 4) * NN + n0 + nn];
        }
        __syncthreads();
        #pragma unroll
        for (int k = 0; k < 16; k++) {
            float4 a4 = *(const float4*)&As[k][ty * 4];
            float4 b4 = *(const float4*)&Bs[k][tx * 4];
            float a[4]  = {a4.x, a4.y, a4.z, a4.w};
            float bb[4] = {b4.x, b4.y, b4.z, b4.w};
            #pragma unroll
            for (int i = 0; i < 4; i++)
                #pragma unroll
                for (int j = 0; j < 4; j++)
                    acc[i][j] += a[i] * bb[j];
        }
        __syncthreads();
    }

    #pragma unroll
    for (int i = 0; i < 4; i++) {
        int o = m0 + ty * 4 + i;
        float bv = bias[o];
        #pragma unroll
        for (int j = 0; j < 4; j++) {
            int n = n0 + tx * 4 + j;
            float v = acc[i][j] + bv;
            if (mat == 1)  // fold rel-pos into K:  energy = q^T(k + pos)
                v += relH[(hd * CH + o) * HH + (n >> 4)]
                   + relW[(hd * CH + o) * WW + (n & 15)];
            Out[(size_t)o * NN + n] = v;
        }
    }
}

// =================================================================================
// Kernel 2: energy[n,m] = sum_c Q[c,n] * KP[c,m]   (per head-batch, 256x256x512)
// =================================================================================
__global__ __launch_bounds__(256) void energy_kernel()
{
    __shared__ float As[16][68];
    __shared__ float Bs[16][68];

    int hb = blockIdx.z;
    const float* Q  = g_Q + (size_t)hb * CH * NN;
    const float* KP = g_K + (size_t)hb * CH * NN;
    float*       E  = g_E + (size_t)hb * NN * NN;

    int n0 = blockIdx.y * 64;   // output rows (q positions)
    int m0 = blockIdx.x * 64;   // output cols (k positions)
    int tid = threadIdx.x;
    int tx = tid & 15, ty = tid >> 4;

    float acc[4][4] = {};

    for (int k0 = 0; k0 < CH; k0 += 16) {
        {
            int nn = tid & 63, cc = tid >> 6;
            #pragma unroll
            for (int r = 0; r < 4; r++)
                As[cc + r * 4][nn] = Q[(size_t)(k0 + cc + r * 4) * NN + n0 + nn];
        }
        {
            int mm = tid & 63, cc = tid >> 6;
            #pragma unroll
            for (int r = 0; r < 4; r++)
                Bs[cc + r * 4][mm] = KP[(size_t)(k0 + cc + r * 4) * NN + m0 + mm];
        }
        __syncthreads();
        #pragma unroll
        for (int k = 0; k < 16; k++) {
            float4 a4 = *(const float4*)&As[k][ty * 4];
            float4 b4 = *(const float4*)&Bs[k][tx * 4];
            float a[4]  = {a4.x, a4.y, a4.z, a4.w};
            float bb[4] = {b4.x, b4.y, b4.z, b4.w};
            #pragma unroll
            for (int i = 0; i < 4; i++)
                #pragma unroll
                for (int j = 0; j < 4; j++)
                    acc[i][j] += a[i] * bb[j];
        }
        __syncthreads();
    }

    #pragma unroll
    for (int i = 0; i < 4; i++)
        #pragma unroll
        for (int j = 0; j < 4; j++)
            E[(size_t)(n0 + ty * 4 + i) * NN + m0 + tx * 4 + j] = acc[i][j];
}

// =================================================================================
// Kernel 3: softmax over last dim (256), in place on g_E. One warp per row.
// =================================================================================
__global__ __launch_bounds__(256) void softmax_kernel()
{
    int warp = threadIdx.x >> 5, lane = threadIdx.x & 31;
    int row  = blockIdx.x * 8 + warp;   // rows total = 5*32*256 = 40960
    float* e = g_E + (size_t)row * NN;

    float4 a = ((float4*)e)[lane];
    float4 b = ((float4*)e)[lane + 32];

    float m = fmaxf(fmaxf(fmaxf(a.x, a.y), fmaxf(a.z, a.w)),
                    fmaxf(fmaxf(b.x, b.y), fmaxf(b.z, b.w)));
    #pragma unroll
    for (int off = 16; off; off >>= 1) m = fmaxf(m, __shfl_xor_sync(0xffffffffu, m, off));

    a.x = __expf(a.x - m); a.y = __expf(a.y - m); a.z = __expf(a.z - m); a.w = __expf(a.w - m);
    b.x = __expf(b.x - m); b.y = __expf(b.y - m); b.z = __expf(b.z - m); b.w = __expf(b.w - m);

    float s = a.x + a.y + a.z + a.w + b.x + b.y + b.z + b.w;
    #pragma unroll
    for (int off = 16; off; off >>= 1) s += __shfl_xor_sync(0xffffffffu, s, off);

    float inv = 1.0f / s;
    a.x *= inv; a.y *= inv; a.z *= inv; a.w *= inv;
    b.x *= inv; b.y *= inv; b.z *= inv; b.w *= inv;
    ((float4*)e)[lane] = a;
    ((float4*)e)[lane + 32] = b;
}

// =================================================================================
// Kernel 4: O[c,n] = sum_m V[c,m] * attn[n,m]   (per head-batch, 512x256x256)
// =================================================================================
__global__ __launch_bounds__(256) void av_kernel()
{
    __shared__ float As[16][68];
    __shared__ float Bs[16][68];

    int hb = blockIdx.z;
    const float* V = g_V + (size_t)hb * CH * NN;
    const float* E = g_E + (size_t)hb * NN * NN;
    float*       O = g_O + (size_t)hb * CH * NN;

    int n0 = blockIdx.x * 64;   // output cols (n)
    int m0 = blockIdx.y * 64;   // output rows (c)
    int tid = threadIdx.x;
    int tx = tid & 15, ty = tid >> 4;

    float acc[4][4] = {};

    for (int k0 = 0; k0 < NN; k0 += 16) {
        {   // A: V[c][m], rows c, k = m
            int kk = tid & 15, c = tid >> 4;
            #pragma unroll
            for (int r = 0; r < 4; r++)
                As[kk][c + r * 16] = V[(size_t)(m0 + c + r * 16) * NN + k0 + kk];
        }
        {   // B: attn^T -> B[k=m][n] = E[n][m]
            int kk = tid & 15, nn = tid >> 4;
            #pragma unroll
            for (int r = 0; r < 4; r++)
                Bs[kk][nn + r * 16] = E[(size_t)(n0 + nn + r * 16) * NN + k0 + kk];
        }
        __syncthreads();
        #pragma unroll
        for (int k = 0; k < 16; k++) {
            float4 a4 = *(const float4*)&As[k][ty * 4];
            float4 b4 = *(const float4*)&Bs[k][tx * 4];
            float a[4]  = {a4.x, a4.y, a4.z, a4.w};
            float bb[4] = {b4.x, b4.y, b4.z, b4.w};
            #pragma unroll
            for (int i = 0; i < 4; i++)
                #pragma unroll
                for (int j = 0; j < 4; j++)
                    acc[i][j] += a[i] * bb[j];
        }
        __syncthreads();
    }

    #pragma unroll
    for (int i = 0; i < 4; i++)
        #pragma unroll
        for (int j = 0; j < 4; j++)
            O[(size_t)(m0 + ty * 4 + i) * NN + n0 + tx * 4 + j] = acc[i][j];
}

// =================================================================================
// Kernel 5: msw gating weights: wgt[b,o,n] = sigmoid(bn(sum_k mswW[o,k]*cat[b,k,n]))
//   cat[b, hd*512+c, n] = g_O[hd][b][c][n].   M=4, K=2560, per-batch N tile of 64.
// =================================================================================
__global__ __launch_bounds__(256) void msw_kernel(
    const float* __restrict__ mswW, const float* __restrict__ g,
    const float* __restrict__ bb,   const float* __restrict__ mm,
    const float* __restrict__ vv)
{
    __shared__ float Bs[32][64];
    __shared__ float As[4][32];

    int b  = blockIdx.y;
    int n0 = blockIdx.x * 64;
    int tid = threadIdx.x;
    int o = tid >> 6, nn = tid & 63;

    float acc = 0.f;
    for (int k0 = 0; k0 < CC5; k0 += 32) {
        if (tid < 128) {
            int oo = tid >> 5, kk = tid & 31;
            As[oo][kk] = mswW[oo * CC5 + k0 + kk];
        }
        #pragma unroll
        for (int r = 0; r < 8; r++) {
            int idx = tid + r * 256;
            int kk = idx >> 6, nl = idx & 63;
            int k = k0 + kk;
            int hd = k >> 9, c = k & 511;
            Bs[kk][nl] = g_O[(size_t)((hd * BATCH + b) * CH + c) * NN + n0 + nl];
        }
        __syncthreads();
        #pragma unroll
        for (int kk = 0; kk < 32; kk++) acc += As[o][kk] * Bs[kk][nn];
        __syncthreads();
    }

    float z = (acc - mm[o]) * (g[o] * rsqrtf(vv[o] + BN_EPS)) + bb[o];
    float w = 1.f / (1.f + __expf(-z));
    g_WGT[(b * 4 + o) * NN + n0 + nn] = w;
}

// =================================================================================
// Kernel 5b: x_ms = w0*O0 + w1*O1 + w2*O2 + w3*O3 + O4   (elementwise)
// =================================================================================
__global__ __launch_bounds__(256) void combine_kernel()
{
    int idx = blockIdx.x * 256 + threadIdx.x;     // [0, B*CH*NN)
    if (idx >= BATCH * CH * NN) return;
    int n = idx & 255;
    int b = idx >> 17;                            // idx >> 8 gives b*CH+c; >>9 more
    const float* w = g_WGT + b * 4 * NN;
    size_t hstride = (size_t)BATCH * CH * NN;
    size_t off = (size_t)idx;
    float r = g_O[4 * hstride + off]
            + w[0 * NN + n] * g_O[off]
            + w[1 * NN + n] * g_O[hstride + off]
            + w[2 * NN + n] * g_O[2 * hstride + off]
            + w[3 * NN + n] * g_O[3 * hstride + off];
    g_MS[off] = r;
}

// =================================================================================
// Kernel 6: conv3x3 SAME as implicit GEMM: per batch 512 x 4608 x 256
//   B operand materialized on the fly with zero padding.
// =================================================================================
__global__ __launch_bounds__(256) void conv_kernel(const float* __restrict__ fusW)
{
    __shared__ float As[16][68];
    __shared__ float Bs[16][68];

    int b  = blockIdx.z;
    int m0 = blockIdx.y * 64;    // output channel tile
    int n0 = blockIdx.x * 64;    // spatial tile
    const float* X = g_MS + (size_t)b * CH * NN;

    int tid = threadIdx.x;
    int tx = tid & 15, ty = tid >> 4;
    float acc[4][4] = {};

    for (int k0 = 0; k0 < KCONV; k0 += 16) {
        {   // A: fusW [o][ci][kh][kw] row-major -> [o][k], k = ci*9 + kh*3 + kw
            int kk = tid & 15, o = tid >> 4;
            #pragma unroll
            for (int r = 0; r < 4; r++)
                As[kk][o + r * 16] = fusW[(size_t)(m0 + o + r * 16) * KCONV + k0 + kk];
        }
        {   // B: im2col on the fly with padding
            #pragma unroll
            for (int r = 0; r < 4; r++) {
                int idx = tid + r * 256;
                int nn = idx & 63, kk = idx >> 6;
                int k = k0 + kk;
                int ci = k / 9;
                int rr = k - ci * 9;
                int kh = rr / 3, kw = rr - kh * 3;
                int n = n0 + nn;
                int y = (n >> 4) + kh - 1;
                int x = (n & 15) + kw - 1;
                float v = 0.f;
                if ((unsigned)y < 16u && (unsigned)x < 16u)
                    v = X[(size_t)ci * NN + (y << 4) + x];
                Bs[kk][nn] = v;
            }
        }
        __syncthreads();
        #pragma unroll
        for (int k = 0; k < 16; k++) {
            float4 a4 = *(const float4*)&As[k][ty * 4];
            float4 b4 = *(const float4*)&Bs[k][tx * 4];
            float a[4]  = {a4.x, a4.y, a4.z, a4.w};
            float bb[4] = {b4.x, b4.y, b4.z, b4.w};
            #pragma unroll
            for (int i = 0; i < 4; i++)
                #pragma unroll
                for (int j = 0; j < 4; j++)
                    acc[i][j] += a[i] * bb[j];
        }
        __syncthreads();
    }

    #pragma unroll
    for (int i = 0; i < 4; i++)
        #pragma unroll
        for (int j = 0; j < 4; j++)
            g_CV[(size_t)(b * CH + m0 + ty * 4 + i) * NN + n0 + tx * 4 + j] = acc[i][j];
}

// =================================================================================
// Kernel 7: out = relu(bn_top( relu(bn_fus(conv_out)) + x ))
// =================================================================================
__global__ __launch_bounds__(256) void final_kernel(
    const float* __restrict__ x,
    const float* __restrict__ fg, const float* __restrict__ fb,
    const float* __restrict__ fm, const float* __restrict__ fv,
    const float* __restrict__ tg, const float* __restrict__ tb,
    const float* __restrict__ tm, const float* __restrict__ tv,
    float* __restrict__ out)
{
    int idx = blockIdx.x * 256 + threadIdx.x;
    if (idx >= BATCH * CH * NN) return;
    int c = (idx >> 8) & 511;
    float t = g_CV[idx];
    t = (t - fm[c]) * (fg[c] * rsqrtf(fv[c] + BN_EPS)) + fb[c];
    t = fmaxf(t, 0.f);
    t += x[idx];
    t = (t - tm[c]) * (tg[c] * rsqrtf(tv[c] + BN_EPS)) + tb[c];
    out[idx] = fmaxf(t, 0.f);
}

// =================================================================================
extern "C" void kernel_launch(void* const* d_in, const int* in_sizes, int n_in,
                              void* d_out, int out_size)
{
    const float* x0   = (const float*)d_in[0];
    const float* x1   = (const float*)d_in[1];
    const float* x2   = (const float*)d_in[2];
    const float* x3   = (const float*)d_in[3];
    const float* x4   = (const float*)d_in[4];
    const float* qW   = (const float*)d_in[5];
    const float* qB   = (const float*)d_in[6];
    const float* kW   = (const float*)d_in[7];
    const float* kB   = (const float*)d_in[8];
    const float* vW   = (const float*)d_in[9];
    const float* vB   = (const float*)d_in[10];
    const float* relH = (const float*)d_in[11];
    const float* relW = (const float*)d_in[12];
    const float* mswW = (const float*)d_in[13];
    const float* mswg = (const float*)d_in[14];
    const float* mswb = (const float*)d_in[15];
    const float* mswm = (const float*)d_in[16];
    const float* mswv = (const float*)d_in[17];
    const float* fusW = (const float*)d_in[18];
    const float* fusg = (const float*)d_in[19];
    const float* fusb = (const float*)d_in[20];
    const float* fusm = (const float*)d_in[21];
    const float* fusv = (const float*)d_in[22];
    const float* topg = (const float*)d_in[23];
    const float* topb = (const float*)d_in[24];
    const float* topm = (const float*)d_in[25];
    const float* topv = (const float*)d_in[26];
    float* out = (float*)d_out;

    // 1. Q/K/V projections (pos folded into K)
    qkv_kernel<<<dim3(NN / 64, CH / 64, 3 * NHEADS * BATCH), 256>>>(
        x0, x1, x2, x3, x4, qW, qB, kW, kB, vW, vB, relH, relW);

    // 2. energy = Q^T (K + pos)
    energy_kernel<<<dim3(NN / 64, NN / 64, NHEADS * BATCH), 256>>>();

    // 3. softmax
    softmax_kernel<<<(NHEADS * BATCH * NN) / 8, 256>>>();

    // 4. O = V @ attn^T
    av_kernel<<<dim3(NN / 64, CH / 64, NHEADS * BATCH), 256>>>();

    // 5. gating weights + combine
    msw_kernel<<<dim3(NN / 64, BATCH), 256>>>(mswW, mswg, mswb, mswm, mswv);
    combine_kernel<<<(BATCH * CH * NN) / 256, 256>>>();

    // 6. conv3x3 (implicit GEMM)
    conv_kernel<<<dim3(NN / 64, CH / 64, BATCH), 256>>>(fusW);

    // 7. final fused bn/relu/add/bn/relu
    final_kernel<<<(BATCH * CH * NN) / 256, 256>>>(
        x4, fusg, fusb, fusm, fusv, topg, topb, topm, topv, out);
}

// round 3
// speedup vs baseline: 2.5031x; 2.5031x over previous
#include <cuda_runtime.h>
#include <cstdint>

#define NHEADS 5
#define BATCH  32
#define CH     512
#define NN     256
#define KCONV  4608
#define BN_EPS 1e-5f

// ---------------- scratch (device globals) ----------------
__device__ float g_XT[(size_t)NHEADS * BATCH * NN * CH];   // x transposed [hb][n][c]
__device__ float g_Qt[(size_t)NHEADS * BATCH * NN * CH];   // Q token-major [hb][n][c]
__device__ float g_Kt[(size_t)NHEADS * BATCH * NN * CH];   // K+pos token-major
__device__ float g_V [(size_t)NHEADS * BATCH * CH * NN];   // V channel-major [hb][c][m]
__device__ float g_E [(size_t)NHEADS * BATCH * NN * NN];   // energy/attn [hb][n][m]
__device__ float g_Ot[(size_t)NHEADS * BATCH * NN * CH];   // attn out token-major
__device__ float g_WGT[BATCH * 4 * NN];
__device__ float g_MS[(size_t)BATCH * NN * CH];            // x_ms token-major [b][n][c]
__device__ float g_CV[(size_t)BATCH * CH * NN];            // conv out channel-major
__device__ float g_Wp[(size_t)CH * KCONV];                 // permuted conv weights

// ---------------- low-level helpers ----------------
__device__ __forceinline__ uint32_t smem_u32(const void* p) {
    uint32_t a;
    asm("{ .reg .u64 t; cvta.to.shared.u64 t, %1; cvt.u32.u64 %0, t; }" : "=r"(a) : "l"(p));
    return a;
}
__device__ __forceinline__ void cpa16(uint32_t s, const void* g, int bytes) {
    asm volatile("cp.async.cg.shared.global [%0], [%1], 16, %2;" :: "r"(s), "l"(g), "r"(bytes));
}
__device__ __forceinline__ void cp_commit() { asm volatile("cp.async.commit_group;"); }
template<int N> __device__ __forceinline__ void cp_wait() {
    asm volatile("cp.async.wait_group %0;" :: "n"(N));
}
__device__ __forceinline__ uint32_t f2tf(float x) {
    uint32_t r; asm("cvt.rna.tf32.f32 %0, %1;" : "=r"(r) : "f"(x)); return r;
}
__device__ __forceinline__ void mma8(float* c, const uint32_t* a, const uint32_t* b) {
    asm volatile("mma.sync.aligned.m16n8k8.row.col.f32.tf32.tf32.f32 "
        "{%0,%1,%2,%3}, {%4,%5,%6,%7}, {%8,%9}, {%0,%1,%2,%3};"
        : "+f"(c[0]), "+f"(c[1]), "+f"(c[2]), "+f"(c[3])
        : "r"(a[0]), "r"(a[1]), "r"(a[2]), "r"(a[3]), "r"(b[0]), "r"(b[1]));
}

// ---------------- smem tile loaders (128 rows x 32 floats, stride 36) ----------------
#define ASZ (128 * 36)
#define STG (2 * ASZ)
#define SMEM_BYTES (2 * STG * 4)

__device__ __forceinline__ void ld_tile(float* smT, const float* g, int ld, int tid) {
    #pragma unroll
    for (int i = 0; i < 4; i++) {
        int idx = tid + i * 256;
        int r = idx >> 3, q = idx & 7;
        cpa16(smem_u32(smT + r * 36 + q * 4), g + (size_t)r * ld + q * 4, 16);
    }
}
__device__ __forceinline__ void ld_conv(float* smT, const float* MSb, int n0, int ch, int tid) {
    int s = ch >> 4;
    int cib = (ch & 15) * 32;
    int kh = s / 3, kw = s - kh * 3;
    #pragma unroll
    for (int i = 0; i < 4; i++) {
        int idx = tid + i * 256;
        int r = idx >> 3, q = idx & 7;
        int n = n0 + r;
        int y = (n >> 4) + kh - 1, x = (n & 15) + kw - 1;
        bool ok = ((unsigned)y < 16u) && ((unsigned)x < 16u);
        const float* src = MSb + (ok ? ((y << 4) + x) * CH : 0) + cib + q * 4;
        cpa16(smem_u32(smT + r * 36 + q * 4), src, ok ? 16 : 0);
    }
}

// ---------------- mma compute on one 128x128x32 chunk ----------------
template<bool SPLIT>
__device__ __forceinline__ void compute_chunk(float cacc[4][4][4],
    const float* As, const float* Bs, int wm, int wn, int lr, int lc)
{
    #pragma unroll
    for (int ks = 0; ks < 4; ks++) {
        int kk = ks * 8;
        uint32_t bhi[4][2], blo[4][2];
        #pragma unroll
        for (int nf = 0; nf < 4; nf++) {
            #pragma unroll
            for (int j = 0; j < 2; j++) {
                float bv = Bs[(wn * 32 + nf * 8 + lr) * 36 + kk + lc + j * 4];
                bhi[nf][j] = f2tf(bv);
                if (SPLIT) blo[nf][j] = __float_as_uint(bv - __uint_as_float(bhi[nf][j]));
            }
        }
        #pragma unroll
        for (int mf = 0; mf < 4; mf++) {
            uint32_t ahi[4], alo[4];
            #pragma unroll
            for (int r = 0; r < 4; r++) {
                float av = As[(wm * 64 + mf * 16 + lr + (r & 1) * 8) * 36 + kk + lc + (r >> 1) * 4];
                ahi[r] = f2tf(av);
                if (SPLIT) alo[r] = __float_as_uint(av - __uint_as_float(ahi[r]));
            }
            #pragma unroll
            for (int nf = 0; nf < 4; nf++) {
                mma8(cacc[mf][nf], ahi, bhi[nf]);
                if (SPLIT) {
                    mma8(cacc[mf][nf], ahi, blo[nf]);
                    mma8(cacc[mf][nf], alo, bhi[nf]);
                }
            }
        }
    }
}

// ---------------- full K-loop driver (double-buffered cp.async) ----------------
template<bool SPLIT, bool CONV>
__device__ __forceinline__ void run_gemm(float cacc[4][4][4], float* sm,
    const float* Aeff, int lda, const float* Beff, int ldb,
    int nchunks, const float* MSb, int n0, int tid)
{
    ld_tile(sm, Aeff, lda, tid);
    if (CONV) ld_conv(sm + ASZ, MSb, n0, 0, tid);
    else      ld_tile(sm + ASZ, Beff, ldb, tid);
    cp_commit();

    int wm = (tid >> 5) & 1, wn = tid >> 6, lr = (tid & 31) >> 2, lc = tid & 3;

    for (int c = 0; c < nchunks; c++) {
        if (c + 1 < nchunks) {
            float* d = sm + ((c + 1) & 1) * STG;
            ld_tile(d, Aeff + (c + 1) * 32, lda, tid);
            if (CONV) ld_conv(d + ASZ, MSb, n0, c + 1, tid);
            else      ld_tile(d + ASZ, Beff + (c + 1) * 32, ldb, tid);
            cp_commit();
            cp_wait<1>();
        } else {
            cp_wait<0>();
        }
        __syncthreads();
        const float* As = sm + (c & 1) * STG;
        compute_chunk<SPLIT>(cacc, As, As + ASZ, wm, wn, lr, lc);
        __syncthreads();
    }
}

// =================================================================================
// transpose x [c][n] -> g_XT [hb][n][c]
// =================================================================================
__global__ void transpose_kernel(
    const float* __restrict__ x0, const float* __restrict__ x1,
    const float* __restrict__ x2, const float* __restrict__ x3,
    const float* __restrict__ x4)
{
    __shared__ float t[32][33];
    int hb = blockIdx.z, hd = hb >> 5, b = hb & 31;
    const float* X = (hd == 0 ? x0 : hd == 1 ? x1 : hd == 2 ? x2 : hd == 3 ? x3 : x4)
                     + (size_t)b * CH * NN;
    float* O = g_XT + (size_t)hb * NN * CH;
    int c0 = blockIdx.y * 32, n0 = blockIdx.x * 32;
    int tx = threadIdx.x, ty = threadIdx.y;
    #pragma unroll
    for (int i = 0; i < 32; i += 8)
        t[ty + i][tx] = X[(size_t)(c0 + ty + i) * NN + n0 + tx];
    __syncthreads();
    #pragma unroll
    for (int i = 0; i < 32; i += 8)
        O[(size_t)(n0 + ty + i) * CH + c0 + tx] = t[tx][ty + i];
}

// =================================================================================
// permute conv weights: g_Wp[o][s*512+ci] = fusW[o][ci*9+s]
// =================================================================================
__global__ void permW_kernel(const float* __restrict__ fusW)
{
    int o = blockIdx.x;
    for (int k = threadIdx.x; k < KCONV; k += 256) {
        int s = k >> 9, ci = k & 511;
        g_Wp[(size_t)o * KCONV + k] = fusW[(size_t)o * KCONV + ci * 9 + s];
    }
}

// =================================================================================
// Q/K projections (split tf32): D[n][o] = Xt[n][:] . W[o][:]
// =================================================================================
__global__ __launch_bounds__(256, 2) void qk_mma(
    const float* __restrict__ qW, const float* __restrict__ qB,
    const float* __restrict__ kW, const float* __restrict__ kB,
    const float* __restrict__ relH, const float* __restrict__ relW)
{
    extern __shared__ float sm[];
    int z = blockIdx.z;
    int isK = z >= NHEADS * BATCH;
    int hb = isK ? z - NHEADS * BATCH : z;
    int hd = hb >> 5;
    const float* W    = (isK ? kW : qW) + (size_t)hd * CH * CH;
    const float* bias = (isK ? kB : qB) + hd * CH;
    const float* Xt = g_XT + (size_t)hb * NN * CH;
    int rbase = blockIdx.y * 128;   // n
    int cbase = blockIdx.x * 128;   // o
    int tid = threadIdx.x;

    float acc[4][4][4] = {};
    run_gemm<true, false>(acc, sm, Xt + (size_t)rbase * CH, CH,
                          W + (size_t)cbase * CH, CH, 16, nullptr, 0, tid);

    int wm = (tid >> 5) & 1, wn = tid >> 6, lr = (tid & 31) >> 2, lc = tid & 3;
    float* dst = (isK ? g_Kt : g_Qt) + (size_t)hb * NN * CH;
    int hdC = hd * CH;
    #pragma unroll
    for (int mf = 0; mf < 4; mf++) {
        #pragma unroll
        for (int nf = 0; nf < 4; nf++) {
            int o = cbase + wn * 32 + nf * 8 + lc * 2;
            float b0 = bias[o], b1 = bias[o + 1];
            #pragma unroll
            for (int rh = 0; rh < 2; rh++) {
                int n = rbase + wm * 64 + mf * 16 + lr + rh * 8;
                float vx = acc[mf][nf][rh * 2 + 0] + b0;
                float vy = acc[mf][nf][rh * 2 + 1] + b1;
                if (isK) {
                    int yy = n >> 4, xx = n & 15;
                    vx += relH[(hdC + o) * 16 + yy] + relW[(hdC + o) * 16 + xx];
                    vy += relH[(hdC + o + 1) * 16 + yy] + relW[(hdC + o + 1) * 16 + xx];
                }
                *(float2*)(dst + (size_t)n * CH + o) = make_float2(vx, vy);
            }
        }
    }
}

// =================================================================================
// V projection (rna tf32): D[o][m] = W[o][:] . Xt[m][:]
// =================================================================================
__global__ __launch_bounds__(256, 2) void v_mma(
    const float* __restrict__ vW, const float* __restrict__ vB)
{
    extern __shared__ float sm[];
    int hb = blockIdx.z, hd = hb >> 5;
    const float* W = vW + (size_t)hd * CH * CH;
    const float* Xt = g_XT + (size_t)hb * NN * CH;
    int rbase = blockIdx.y * 128;   // o
    int cbase = blockIdx.x * 128;   // m
    int tid = threadIdx.x;

    float acc[4][4][4] = {};
    run_gemm<false, false>(acc, sm, W + (size_t)rbase * CH, CH,
                           Xt + (size_t)cbase * CH, CH, 16, nullptr, 0, tid);

    int wm = (tid >> 5) & 1, wn = tid >> 6, lr = (tid & 31) >> 2, lc = tid & 3;
    const float* bias = vB + hd * CH;
    float* dst = g_V + (size_t)hb * CH * NN;
    #pragma unroll
    for (int mf = 0; mf < 4; mf++) {
        #pragma unroll
        for (int nf = 0; nf < 4; nf++) {
            int m = cbase + wn * 32 + nf * 8 + lc * 2;
            #pragma unroll
            for (int rh = 0; rh < 2; rh++) {
                int o = rbase + wm * 64 + mf * 16 + lr + rh * 8;
                float bv = bias[o];
                *(float2*)(dst + (size_t)o * NN + m) =
                    make_float2(acc[mf][nf][rh * 2 + 0] + bv, acc[mf][nf][rh * 2 + 1] + bv);
            }
        }
    }
}

// =================================================================================
// energy (split tf32): E[n][m] = Qt[n][:] . Kt[m][:]
// =================================================================================
__global__ __launch_bounds__(256, 2) void energy_mma()
{
    extern __shared__ float sm[];
    int hb = blockIdx.z;
    const float* Q = g_Qt + (size_t)hb * NN * CH;
    const float* K = g_Kt + (size_t)hb * NN * CH;
    int rbase = blockIdx.y * 128, cbase = blockIdx.x * 128;
    int tid = threadIdx.x;

    float acc[4][4][4] = {};
    run_gemm<true, false>(acc, sm, Q + (size_t)rbase * CH, CH,
                          K + (size_t)cbase * CH, CH, 16, nullptr, 0, tid);

    int wm = (tid >> 5) & 1, wn = tid >> 6, lr = (tid & 31) >> 2, lc = tid & 3;
    float* dst = g_E + (size_t)hb * NN * NN;
    #pragma unroll
    for (int mf = 0; mf < 4; mf++) {
        #pragma unroll
        for (int nf = 0; nf < 4; nf++) {
            int m = cbase + wn * 32 + nf * 8 + lc * 2;
            #pragma unroll
            for (int rh = 0; rh < 2; rh++) {
                int n = rbase + wm * 64 + mf * 16 + lr + rh * 8;
                *(float2*)(dst + (size_t)n * NN + m) =
                    make_float2(acc[mf][nf][rh * 2 + 0], acc[mf][nf][rh * 2 + 1]);
            }
        }
    }
}

// =================================================================================
// softmax over last dim (256), in place on g_E
// =================================================================================
__global__ __launch_bounds__(256) void softmax_kernel()
{
    int warp = threadIdx.x >> 5, lane = threadIdx.x & 31;
    int row = blockIdx.x * 8 + warp;
    float* e = g_E + (size_t)row * NN;

    float4 a = ((float4*)e)[lane];
    float4 b = ((float4*)e)[lane + 32];
    float m = fmaxf(fmaxf(fmaxf(a.x, a.y), fmaxf(a.z, a.w)),
                    fmaxf(fmaxf(b.x, b.y), fmaxf(b.z, b.w)));
    #pragma unroll
    for (int off = 16; off; off >>= 1) m = fmaxf(m, __shfl_xor_sync(0xffffffffu, m, off));
    a.x = __expf(a.x - m); a.y = __expf(a.y - m); a.z = __expf(a.z - m); a.w = __expf(a.w - m);
    b.x = __expf(b.x - m); b.y = __expf(b.y - m); b.z = __expf(b.z - m); b.w = __expf(b.w - m);
    float s = a.x + a.y + a.z + a.w + b.x + b.y + b.z + b.w;
    #pragma unroll
    for (int off = 16; off; off >>= 1) s += __shfl_xor_sync(0xffffffffu, s, off);
    float inv = 1.0f / s;
    a.x *= inv; a.y *= inv; a.z *= inv; a.w *= inv;
    b.x *= inv; b.y *= inv; b.z *= inv; b.w *= inv;
    ((float4*)e)[lane] = a;
    ((float4*)e)[lane + 32] = b;
}

// =================================================================================
// AV (rna tf32): Ot[n][c] = attn[n][:] . V[c][:]   (K = 256)
// =================================================================================
__global__ __launch_bounds__(256, 2) void av_mma()
{
    extern __shared__ float sm[];
    int hb = blockIdx.z;
    const float* A = g_E + (size_t)hb * NN * NN;
    const float* V = g_V + (size_t)hb * CH * NN;
    int rbase = blockIdx.y * 128;   // n
    int cbase = blockIdx.x * 128;   // c
    int tid = threadIdx.x;

    float acc[4][4][4] = {};
    run_gemm<false, false>(acc, sm, A + (size_t)rbase * NN, NN,
                           V + (size_t)cbase * NN, NN, 8, nullptr, 0, tid);

    int wm = (tid >> 5) & 1, wn = tid >> 6, lr = (tid & 31) >> 2, lc = tid & 3;
    float* dst = g_Ot + (size_t)hb * NN * CH;
    #pragma unroll
    for (int mf = 0; mf < 4; mf++) {
        #pragma unroll
        for (int nf = 0; nf < 4; nf++) {
            int c = cbase + wn * 32 + nf * 8 + lc * 2;
            #pragma unroll
            for (int rh = 0; rh < 2; rh++) {
                int n = rbase + wm * 64 + mf * 16 + lr + rh * 8;
                *(float2*)(dst + (size_t)n * CH + c) =
                    make_float2(acc[mf][nf][rh * 2 + 0], acc[mf][nf][rh * 2 + 1]);
            }
        }
    }
}

// =================================================================================
// msw gating: one warp per (b, n)
// =================================================================================
__global__ __launch_bounds__(256) void msw_kernel(
    const float* __restrict__ mswW, const float* __restrict__ gg,
    const float* __restrict__ bbt,  const float* __restrict__ mmn,
    const float* __restrict__ vvr)
{
    int b = blockIdx.y;
    int n = blockIdx.x * 8 + (threadIdx.x >> 5);
    int lane = threadIdx.x & 31;
    float a0 = 0.f, a1 = 0.f, a2 = 0.f, a3 = 0.f;
    #pragma unroll
    for (int hd = 0; hd < NHEADS; hd++) {
        const float* base = g_Ot + ((size_t)(hd * BATCH + b) * NN + n) * CH;
        const float* w = mswW + hd * CH;
        for (int c = lane; c < CH; c += 32) {
            float xv = base[c];
            a0 += xv * w[c];
            a1 += xv * w[2560 + c];
            a2 += xv * w[2 * 2560 + c];
            a3 += xv * w[3 * 2560 + c];
        }
    }
    #pragma unroll
    for (int off = 16; off; off >>= 1) {
        a0 += __shfl_xor_sync(0xffffffffu, a0, off);
        a1 += __shfl_xor_sync(0xffffffffu, a1, off);
        a2 += __shfl_xor_sync(0xffffffffu, a2, off);
        a3 += __shfl_xor_sync(0xffffffffu, a3, off);
    }
    if (lane < 4) {
        float acc = lane == 0 ? a0 : lane == 1 ? a1 : lane == 2 ? a2 : a3;
        float z = (acc - mmn[lane]) * (gg[lane] * rsqrtf(vvr[lane] + BN_EPS)) + bbt[lane];
        g_WGT[(b * 4 + lane) * NN + n] = 1.f / (1.f + __expf(-z));
    }
}

// =================================================================================
// combine: x_ms[b][n][c] = Ot4 + sum_i w_i[n] * Ot_i
// =================================================================================
__global__ __launch_bounds__(256) void combine_kernel()
{
    int idx = blockIdx.x * 256 + threadIdx.x;
    int b = idx >> 17;
    int n = (idx >> 9) & 255;
    const float* w = g_WGT + b * 4 * NN;
    size_t hs = (size_t)BATCH * NN * CH;
    size_t off = (size_t)idx;
    float r = g_Ot[4 * hs + off]
            + w[n]          * g_Ot[off]
            + w[NN + n]     * g_Ot[hs + off]
            + w[2 * NN + n] * g_Ot[2 * hs + off]
            + w[3 * NN + n] * g_Ot[3 * hs + off];
    g_MS[off] = r;
}

// =================================================================================
// conv3x3 implicit GEMM (rna tf32): D[o][n], K = 4608
// =================================================================================
__global__ __launch_bounds__(256, 2) void conv_mma()
{
    extern __shared__ float sm[];
    int b = blockIdx.z;
    int rbase = blockIdx.y * 128;   // o
    int cbase = blockIdx.x * 128;   // n
    const float* MSb = g_MS + (size_t)b * NN * CH;
    int tid = threadIdx.x;

    float acc[4][4][4] = {};
    run_gemm<false, true>(acc, sm, g_Wp + (size_t)rbase * KCONV, KCONV,
                          nullptr, 0, 144, MSb, cbase, tid);

    int wm = (tid >> 5) & 1, wn = tid >> 6, lr = (tid & 31) >> 2, lc = tid & 3;
    float* dst = g_CV + (size_t)b * CH * NN;
    #pragma unroll
    for (int mf = 0; mf < 4; mf++) {
        #pragma unroll
        for (int nf = 0; nf < 4; nf++) {
            int n = cbase + wn * 32 + nf * 8 + lc * 2;
            #pragma unroll
            for (int rh = 0; rh < 2; rh++) {
                int o = rbase + wm * 64 + mf * 16 + lr + rh * 8;
                *(float2*)(dst + (size_t)o * NN + n) =
                    make_float2(acc[mf][nf][rh * 2 + 0], acc[mf][nf][rh * 2 + 1]);
            }
        }
    }
}

// =================================================================================
// final: out = relu(bn_top(relu(bn_fus(conv)) + x))
// =================================================================================
__global__ __launch_bounds__(256) void final_kernel(
    const float* __restrict__ x,
    const float* __restrict__ fg, const float* __restrict__ fb,
    const float* __restrict__ fm, const float* __restrict__ fv,
    const float* __restrict__ tg, const float* __restrict__ tb,
    const float* __restrict__ tm, const float* __restrict__ tv,
    float* __restrict__ out)
{
    int idx = blockIdx.x * 256 + threadIdx.x;
    int c = (idx >> 8) & 511;
    float t = g_CV[idx];
    t = (t - fm[c]) * (fg[c] * rsqrtf(fv[c] + BN_EPS)) + fb[c];
    t = fmaxf(t, 0.f);
    t += x[idx];
    t = (t - tm[c]) * (tg[c] * rsqrtf(tv[c] + BN_EPS)) + tb[c];
    out[idx] = fmaxf(t, 0.f);
}

// =================================================================================
extern "C" void kernel_launch(void* const* d_in, const int* in_sizes, int n_in,
                              void* d_out, int out_size)
{
    const float* x0   = (const float*)d_in[0];
    const float* x1   = (const float*)d_in[1];
    const float* x2   = (const float*)d_in[2];
    const float* x3   = (const float*)d_in[3];
    const float* x4   = (const float*)d_in[4];
    const float* qW   = (const float*)d_in[5];
    const float* qB   = (const float*)d_in[6];
    const float* kW   = (const float*)d_in[7];
    const float* kB   = (const float*)d_in[8];
    const float* vW   = (const float*)d_in[9];
    const float* vB   = (const float*)d_in[10];
    const float* relH = (const float*)d_in[11];
    const float* relW = (const float*)d_in[12];
    const float* mswW = (const float*)d_in[13];
    const float* mswg = (const float*)d_in[14];
    const float* mswb = (const float*)d_in[15];
    const float* mswm = (const float*)d_in[16];
    const float* mswv = (const float*)d_in[17];
    const float* fusW = (const float*)d_in[18];
    const float* fusg = (const float*)d_in[19];
    const float* fusb = (const float*)d_in[20];
    const float* fusm = (const float*)d_in[21];
    const float* fusv = (const float*)d_in[22];
    const float* topg = (const float*)d_in[23];
    const float* topb = (const float*)d_in[24];
    const float* topm = (const float*)d_in[25];
    const float* topv = (const float*)d_in[26];
    float* out = (float*)d_out;

    cudaFuncSetAttribute(qk_mma,     cudaFuncAttributeMaxDynamicSharedMemorySize, SMEM_BYTES);
    cudaFuncSetAttribute(v_mma,      cudaFuncAttributeMaxDynamicSharedMemorySize, SMEM_BYTES);
    cudaFuncSetAttribute(energy_mma, cudaFuncAttributeMaxDynamicSharedMemorySize, SMEM_BYTES);
    cudaFuncSetAttribute(av_mma,     cudaFuncAttributeMaxDynamicSharedMemorySize, SMEM_BYTES);
    cudaFuncSetAttribute(conv_mma,   cudaFuncAttributeMaxDynamicSharedMemorySize, SMEM_BYTES);

    transpose_kernel<<<dim3(8, 16, NHEADS * BATCH), dim3(32, 8)>>>(x0, x1, x2, x3, x4);
    permW_kernel<<<CH, 256>>>(fusW);

    // Q,K projections: D[n][o], rows n=256 (y:2), cols o=512 (x:4), z = {Q,K} x 160
    qk_mma<<<dim3(4, 2, 2 * NHEADS * BATCH), 256, SMEM_BYTES>>>(qW, qB, kW, kB, relH, relW);

    // V projection: D[o][m], rows o=512 (y:4), cols m=256 (x:2)
    v_mma<<<dim3(2, 4, NHEADS * BATCH), 256, SMEM_BYTES>>>(vW, vB);

    // energy: D[n][m], 256x256
    energy_mma<<<dim3(2, 2, NHEADS * BATCH), 256, SMEM_BYTES>>>();

    softmax_kernel<<<(NHEADS * BATCH * NN) / 8, 256>>>();

    // AV: D[n][c], rows n=256 (y:2), cols c=512 (x:4)
    av_mma<<<dim3(4, 2, NHEADS * BATCH), 256, SMEM_BYTES>>>();

    msw_kernel<<<dim3(NN / 8, BATCH), 256>>>(mswW, mswg, mswb, mswm, mswv);
    combine_kernel<<<(BATCH * NN * CH) / 256, 256>>>();

    // conv: D[o][n], rows o=512 (y:4), cols n=256 (x:2)
    conv_mma<<<dim3(2, 4, BATCH), 256, SMEM_BYTES>>>();

    final_kernel<<<(BATCH * CH * NN) / 256, 256>>>(
        x4, fusg, fusb, fusm, fusv, topg, topb, topm, topv, out);
}

// round 6
// speedup vs baseline: 2.9700x; 1.1865x over previous
#include <cuda_runtime.h>
#include <cuda_bf16.h>
#include <cstdint>

#define NHEADS 5
#define BATCH  32
#define CH     512
#define NN     256
#define KCONV  4608
#define BN_EPS 1e-5f

typedef __nv_bfloat16 bf16;
typedef __nv_bfloat162 bf162;

// ---------------- scratch (device globals) ----------------
__device__ bf16 g_XTh[(size_t)NHEADS * BATCH * NN * CH];   // x transposed hi [hb][n][c]
__device__ bf16 g_XTl[(size_t)NHEADS * BATCH * NN * CH];   // lo
__device__ bf16 g_Wh[(size_t)3 * NHEADS * CH * CH];        // q/k/v weights hi [mat][hd][o][c]
__device__ bf16 g_Wl[(size_t)3 * NHEADS * CH * CH];
__device__ bf16 g_Qh[(size_t)NHEADS * BATCH * NN * CH];    // Q token-major hi
__device__ bf16 g_Ql[(size_t)NHEADS * BATCH * NN * CH];
__device__ bf16 g_Kh[(size_t)NHEADS * BATCH * NN * CH];    // K+pos token-major hi
__device__ bf16 g_Kl[(size_t)NHEADS * BATCH * NN * CH];
__device__ float g_V [(size_t)NHEADS * BATCH * CH * NN];   // V channel-major fp32
__device__ float g_E [(size_t)NHEADS * BATCH * NN * NN];   // energy/attn fp32
__device__ float g_Ot[(size_t)NHEADS * BATCH * NN * CH];   // attn out token-major fp32
__device__ float g_WGT[BATCH * 4 * NN];
__device__ float g_MS[(size_t)BATCH * NN * CH];            // x_ms token-major fp32
__device__ float g_CV[(size_t)BATCH * CH * NN];            // conv out channel-major
__device__ float g_Wp[(size_t)CH * KCONV];                 // permuted conv weights fp32

// ---------------- low-level helpers ----------------
__device__ __forceinline__ uint32_t smem_u32(const void* p) {
    uint32_t a;
    asm("{ .reg .u64 t; cvta.to.shared.u64 t, %1; cvt.u32.u64 %0, t; }" : "=r"(a) : "l"(p));
    return a;
}
__device__ __forceinline__ void cpa16(uint32_t s, const void* g, int bytes) {
    asm volatile("cp.async.cg.shared.global [%0], [%1], 16, %2;" :: "r"(s), "l"(g), "r"(bytes));
}
__device__ __forceinline__ void cp_commit() { asm volatile("cp.async.commit_group;"); }
template<int N> __device__ __forceinline__ void cp_wait() {
    asm volatile("cp.async.wait_group %0;" :: "n"(N));
}
__device__ __forceinline__ uint32_t f2tf(float x) {
    uint32_t r; asm("cvt.rna.tf32.f32 %0, %1;" : "=r"(r) : "f"(x)); return r;
}
__device__ __forceinline__ void mma8(float* c, const uint32_t* a, const uint32_t* b) {
    asm volatile("mma.sync.aligned.m16n8k8.row.col.f32.tf32.tf32.f32 "
        "{%0,%1,%2,%3}, {%4,%5,%6,%7}, {%8,%9}, {%0,%1,%2,%3};"
        : "+f"(c[0]), "+f"(c[1]), "+f"(c[2]), "+f"(c[3])
        : "r"(a[0]), "r"(a[1]), "r"(a[2]), "r"(a[3]), "r"(b[0]), "r"(b[1]));
}
__device__ __forceinline__ void mma16(float* c, const uint32_t* a, const uint32_t* b) {
    asm volatile("mma.sync.aligned.m16n8k16.row.col.f32.bf16.bf16.f32 "
        "{%0,%1,%2,%3}, {%4,%5,%6,%7}, {%8,%9}, {%0,%1,%2,%3};"
        : "+f"(c[0]), "+f"(c[1]), "+f"(c[2]), "+f"(c[3])
        : "r"(a[0]), "r"(a[1]), "r"(a[2]), "r"(a[3]), "r"(b[0]), "r"(b[1]));
}
__device__ __forceinline__ bf16 bhi(float v) { return __float2bfloat16_rn(v); }
__device__ __forceinline__ bf16 blo(float v, bf16 h) {
    return __float2bfloat16_rn(v - __bfloat162float(h));
}

// ================= bf16-split GEMM machinery =================
// tiles: 128 rows x 32 halves, row stride 40 halves (80B) -> conflict-free frags
#define HSTR 40
#define HTILE (128 * HSTR)
#define HSTAGE (4 * HTILE)
#define SMEMB_BYTES (2 * HSTAGE * 2)    // 81920 B

__device__ __forceinline__ void ld_tile_h(bf16* smT, const bf16* g, int ld, int tid) {
    #pragma unroll
    for (int i = 0; i < 2; i++) {
        int idx = tid + i * 256;
        int r = idx >> 2, q = idx & 3;
        cpa16(smem_u32(smT + r * HSTR + q * 8), g + (size_t)r * ld + q * 8, 16);
    }
}

__device__ __forceinline__ void compute_chunk_bf(float cacc[4][4][4],
    const bf16* S, int wm, int wn, int lr, int lc)
{
    const bf16* Ah = S;
    const bf16* Al = S + HTILE;
    const bf16* Bh = S + 2 * HTILE;
    const bf16* Bl = S + 3 * HTILE;
    #pragma unroll
    for (int ks = 0; ks < 2; ks++) {
        int kk = ks * 16 + 2 * lc;
        uint32_t bh[4][2], bl[4][2];
        #pragma unroll
        for (int nf = 0; nf < 4; nf++) {
            int rb = (wn * 32 + nf * 8 + lr) * HSTR + kk;
            bh[nf][0] = *(const uint32_t*)(Bh + rb);
            bh[nf][1] = *(const uint32_t*)(Bh + rb + 8);
            bl[nf][0] = *(const uint32_t*)(Bl + rb);
            bl[nf][1] = *(const uint32_t*)(Bl + rb + 8);
        }
        #pragma unroll
        for (int mf = 0; mf < 4; mf++) {
            int ra = (wm * 64 + mf * 16 + lr) * HSTR + kk;
            uint32_t ah[4], al[4];
            ah[0] = *(const uint32_t*)(Ah + ra);
            ah[1] = *(const uint32_t*)(Ah + ra + 8 * HSTR);
            ah[2] = *(const uint32_t*)(Ah + ra + 8);
            ah[3] = *(const uint32_t*)(Ah + ra + 8 * HSTR + 8);
            al[0] = *(const uint32_t*)(Al + ra);
            al[1] = *(const uint32_t*)(Al + ra + 8 * HSTR);
            al[2] = *(const uint32_t*)(Al + ra + 8);
            al[3] = *(const uint32_t*)(Al + ra + 8 * HSTR + 8);
            #pragma unroll
            for (int nf = 0; nf < 4; nf++) {
                mma16(cacc[mf][nf], ah, bh[nf]);
                mma16(cacc[mf][nf], ah, bl[nf]);
                mma16(cacc[mf][nf], al, bh[nf]);
            }
        }
    }
}

__device__ __forceinline__ void run_gemm_bf(float cacc[4][4][4], bf16* sm,
    const bf16* Ah, const bf16* Al, int lda,
    const bf16* Bh, const bf16* Bl, int ldb, int nchunks, int tid)
{
    ld_tile_h(sm,             Ah, lda, tid);
    ld_tile_h(sm + HTILE,     Al, lda, tid);
    ld_tile_h(sm + 2 * HTILE, Bh, ldb, tid);
    ld_tile_h(sm + 3 * HTILE, Bl, ldb, tid);
    cp_commit();

    int wm = (tid >> 5) & 1, wn = tid >> 6, lr = (tid & 31) >> 2, lc = tid & 3;

    for (int c = 0; c < nchunks; c++) {
        if (c + 1 < nchunks) {
            bf16* d = sm + ((c + 1) & 1) * HSTAGE;
            int ko = (c + 1) * 32;
            ld_tile_h(d,             Ah + ko, lda, tid);
            ld_tile_h(d + HTILE,     Al + ko, lda, tid);
            ld_tile_h(d + 2 * HTILE, Bh + ko, ldb, tid);
            ld_tile_h(d + 3 * HTILE, Bl + ko, ldb, tid);
            cp_commit();
            cp_wait<1>();
        } else {
            cp_wait<0>();
        }
        __syncthreads();
        compute_chunk_bf(cacc, sm + (c & 1) * HSTAGE, wm, wn, lr, lc);
        __syncthreads();
    }
}

// ================= fp32/tf32 GEMM machinery (AV + conv) =================
#define ASZ (128 * 36)
#define STG (2 * ASZ)
#define SMEM_BYTES (2 * STG * 4)

__device__ __forceinline__ void ld_tile(float* smT, const float* g, int ld, int tid) {
    #pragma unroll
    for (int i = 0; i < 4; i++) {
        int idx = tid + i * 256;
        int r = idx >> 3, q = idx & 7;
        cpa16(smem_u32(smT + r * 36 + q * 4), g + (size_t)r * ld + q * 4, 16);
    }
}
__device__ __forceinline__ void ld_conv(float* smT, const float* MSb, int n0, int ch, int tid) {
    int s = ch >> 4;
    int cib = (ch & 15) * 32;
    int kh = s / 3, kw = s - kh * 3;
    #pragma unroll
    for (int i = 0; i < 4; i++) {
        int idx = tid + i * 256;
        int r = idx >> 3, q = idx & 7;
        int n = n0 + r;
        int y = (n >> 4) + kh - 1, x = (n & 15) + kw - 1;
        bool ok = ((unsigned)y < 16u) && ((unsigned)x < 16u);
        const float* src = MSb + (ok ? ((y << 4) + x) * CH : 0) + cib + q * 4;
        cpa16(smem_u32(smT + r * 36 + q * 4), src, ok ? 16 : 0);
    }
}

__device__ __forceinline__ void compute_chunk_tf(float cacc[4][4][4],
    const float* As, const float* Bs, int wm, int wn, int lr, int lc)
{
    #pragma unroll
    for (int ks = 0; ks < 4; ks++) {
        int kk = ks * 8;
        uint32_t bhv[4][2];
        #pragma unroll
        for (int nf = 0; nf < 4; nf++) {
            #pragma unroll
            for (int j = 0; j < 2; j++)
                bhv[nf][j] = f2tf(Bs[(wn * 32 + nf * 8 + lr) * 36 + kk + lc + j * 4]);
        }
        #pragma unroll
        for (int mf = 0; mf < 4; mf++) {
            uint32_t ahv[4];
            #pragma unroll
            for (int r = 0; r < 4; r++)
                ahv[r] = f2tf(As[(wm * 64 + mf * 16 + lr + (r & 1) * 8) * 36 + kk + lc + (r >> 1) * 4]);
            #pragma unroll
            for (int nf = 0; nf < 4; nf++)
                mma8(cacc[mf][nf], ahv, bhv[nf]);
        }
    }
}

template<bool CONV>
__device__ __forceinline__ void run_gemm_tf(float cacc[4][4][4], float* sm,
    const float* Aeff, int lda, const float* Beff, int ldb,
    int nchunks, const float* MSb, int n0, int tid)
{
    ld_tile(sm, Aeff, lda, tid);
    if (CONV) ld_conv(sm + ASZ, MSb, n0, 0, tid);
    else      ld_tile(sm + ASZ, Beff, ldb, tid);
    cp_commit();

    int wm = (tid >> 5) & 1, wn = tid >> 6, lr = (tid & 31) >> 2, lc = tid & 3;

    for (int c = 0; c < nchunks; c++) {
        if (c + 1 < nchunks) {
            float* d = sm + ((c + 1) & 1) * STG;
            ld_tile(d, Aeff + (c + 1) * 32, lda, tid);
            if (CONV) ld_conv(d + ASZ, MSb, n0, c + 1, tid);
            else      ld_tile(d + ASZ, Beff + (c + 1) * 32, ldb, tid);
            cp_commit();
            cp_wait<1>();
        } else {
            cp_wait<0>();
        }
        __syncthreads();
        const float* As = sm + (c & 1) * STG;
        compute_chunk_tf(cacc, As, As + ASZ, wm, wn, lr, lc);
        __syncthreads();
    }
}

// =================================================================================
// transpose x [c][n] -> XT hi/lo [hb][n][c]
// =================================================================================
__global__ void transpose_kernel(
    const float* __restrict__ x0, const float* __restrict__ x1,
    const float* __restrict__ x2, const float* __restrict__ x3,
    const float* __restrict__ x4)
{
    __shared__ float t[32][33];
    int hb = blockIdx.z, hd = hb >> 5, b = hb & 31;
    const float* X = (hd == 0 ? x0 : hd == 1 ? x1 : hd == 2 ? x2 : hd == 3 ? x3 : x4)
                     + (size_t)b * CH * NN;
    int c0 = blockIdx.y * 32, n0 = blockIdx.x * 32;
    int tx = threadIdx.x, ty = threadIdx.y;
    #pragma unroll
    for (int i = 0; i < 32; i += 8)
        t[ty + i][tx] = X[(size_t)(c0 + ty + i) * NN + n0 + tx];
    __syncthreads();
    size_t base = (size_t)hb * NN * CH;
    #pragma unroll
    for (int i = 0; i < 32; i += 8) {
        float v = t[tx][ty + i];
        bf16 h = bhi(v);
        size_t off = base + (size_t)(n0 + ty + i) * CH + c0 + tx;
        g_XTh[off] = h;
        g_XTl[off] = blo(v, h);
    }
}

// =================================================================================
// split q/k/v weights -> bf16 hi/lo
// =================================================================================
__global__ void wsplit_kernel(const float* __restrict__ qW,
                              const float* __restrict__ kW,
                              const float* __restrict__ vW)
{
    int mat = blockIdx.z;
    const float* src = mat == 0 ? qW : mat == 1 ? kW : vW;
    size_t i = (size_t)blockIdx.x * 256 + threadIdx.x;   // < 5*512*512
    float v = src[i];
    bf16 h = bhi(v);
    size_t o = (size_t)mat * NHEADS * CH * CH + i;
    g_Wh[o] = h;
    g_Wl[o] = blo(v, h);
}

// =================================================================================
// permute conv weights: g_Wp[o][s*512+ci] = fusW[o][ci*9+s]
// =================================================================================
__global__ void permW_kernel(const float* __restrict__ fusW)
{
    int o = blockIdx.x;
    for (int k = threadIdx.x; k < KCONV; k += 256) {
        int s = k >> 9, ci = k & 511;
        g_Wp[(size_t)o * KCONV + k] = fusW[(size_t)o * KCONV + ci * 9 + s];
    }
}

// =================================================================================
// Q/K projections (bf16 split): D[n][o] = Xt[n][:] . W[o][:]
// =================================================================================
__global__ __launch_bounds__(256, 2) void qk_mma(
    const float* __restrict__ qB, const float* __restrict__ kB,
    const float* __restrict__ relH, const float* __restrict__ relW)
{
    extern __shared__ bf16 smh[];
    int z = blockIdx.z;
    int isK = z >= NHEADS * BATCH;
    int hb = isK ? z - NHEADS * BATCH : z;
    int hd = hb >> 5;
    size_t woff = ((size_t)(isK ? 1 : 0) * NHEADS + hd) * CH * CH;
    const float* bias = (isK ? kB : qB) + hd * CH;
    size_t xoff = (size_t)hb * NN * CH;
    int rbase = blockIdx.y * 128;   // n
    int cbase = blockIdx.x * 128;   // o
    int tid = threadIdx.x;

    float acc[4][4][4] = {};
    run_gemm_bf(acc, smh,
                g_XTh + xoff + (size_t)rbase * CH, g_XTl + xoff + (size_t)rbase * CH, CH,
                g_Wh + woff + (size_t)cbase * CH,  g_Wl + woff + (size_t)cbase * CH,  CH,
                16, tid);

    int wm = (tid >> 5) & 1, wn = tid >> 6, lr = (tid & 31) >> 2, lc = tid & 3;
    bf16* dsth = (isK ? g_Kh : g_Qh) + xoff;
    bf16* dstl = (isK ? g_Kl : g_Ql) + xoff;
    int hdC = hd * CH;
    #pragma unroll
    for (int mf = 0; mf < 4; mf++) {
        #pragma unroll
        for (int nf = 0; nf < 4; nf++) {
            int o = cbase + wn * 32 + nf * 8 + lc * 2;
            float b0 = bias[o], b1 = bias[o + 1];
            #pragma unroll
            for (int rh = 0; rh < 2; rh++) {
                int n = rbase + wm * 64 + mf * 16 + lr + rh * 8;
                float vx = acc[mf][nf][rh * 2 + 0] + b0;
                float vy = acc[mf][nf][rh * 2 + 1] + b1;
                if (isK) {
                    int yy = n >> 4, xx = n & 15;
                    vx += relH[(hdC + o) * 16 + yy] + relW[(hdC + o) * 16 + xx];
                    vy += relH[(hdC + o + 1) * 16 + yy] + relW[(hdC + o + 1) * 16 + xx];
                }
                bf16 hx = bhi(vx), hy = bhi(vy);
                size_t off = (size_t)n * CH + o;
                *(bf162*)(dsth + off) = bf162(hx, hy);
                *(bf162*)(dstl + off) = bf162(blo(vx, hx), blo(vy, hy));
            }
        }
    }
}

// =================================================================================
// V projection (bf16 split): D[o][m] = W[o][:] . Xt[m][:], fp32 out
// =================================================================================
__global__ __launch_bounds__(256, 2) void v_mma(const float* __restrict__ vB)
{
    extern __shared__ bf16 smh[];
    int hb = blockIdx.z, hd = hb >> 5;
    size_t woff = ((size_t)2 * NHEADS + hd) * CH * CH;
    size_t xoff = (size_t)hb * NN * CH;
    int rbase = blockIdx.y * 128;   // o
    int cbase = blockIdx.x * 128;   // m
    int tid = threadIdx.x;

    float acc[4][4][4] = {};
    run_gemm_bf(acc, smh,
                g_Wh + woff + (size_t)rbase * CH,  g_Wl + woff + (size_t)rbase * CH,  CH,
                g_XTh + xoff + (size_t)cbase * CH, g_XTl + xoff + (size_t)cbase * CH, CH,
                16, tid);

    int wm = (tid >> 5) & 1, wn = tid >> 6, lr = (tid & 31) >> 2, lc = tid & 3;
    const float* bias = vB + hd * CH;
    float* dst = g_V + (size_t)hb * CH * NN;
    #pragma unroll
    for (int mf = 0; mf < 4; mf++) {
        #pragma unroll
        for (int nf = 0; nf < 4; nf++) {
            int m = cbase + wn * 32 + nf * 8 + lc * 2;
            #pragma unroll
            for (int rh = 0; rh < 2; rh++) {
                int o = rbase + wm * 64 + mf * 16 + lr + rh * 8;
                float bv = bias[o];
                *(float2*)(dst + (size_t)o * NN + m) =
                    make_float2(acc[mf][nf][rh * 2 + 0] + bv, acc[mf][nf][rh * 2 + 1] + bv);
            }
        }
    }
}

// =================================================================================
// energy (bf16 split): E[n][m] = Q[n][:] . K[m][:], fp32 out
// =================================================================================
__global__ __launch_bounds__(256, 2) void energy_mma()
{
    extern __shared__ bf16 smh[];
    int hb = blockIdx.z;
    size_t xoff = (size_t)hb * NN * CH;
    int rbase = blockIdx.y * 128, cbase = blockIdx.x * 128;
    int tid = threadIdx.x;

    float acc[4][4][4] = {};
    run_gemm_bf(acc, smh,
                g_Qh + xoff + (size_t)rbase * CH, g_Ql + xoff + (size_t)rbase * CH, CH,
                g_Kh + xoff + (size_t)cbase * CH, g_Kl + xoff + (size_t)cbase * CH, CH,
                16, tid);

    int wm = (tid >> 5) & 1, wn = tid >> 6, lr = (tid & 31) >> 2, lc = tid & 3;
    float* dst = g_E + (size_t)hb * NN * NN;
    #pragma unroll
    for (int mf = 0; mf < 4; mf++) {
        #pragma unroll
        for (int nf = 0; nf < 4; nf++) {
            int m = cbase + wn * 32 + nf * 8 + lc * 2;
            #pragma unroll
            for (int rh = 0; rh < 2; rh++) {
                int n = rbase + wm * 64 + mf * 16 + lr + rh * 8;
                *(float2*)(dst + (size_t)n * NN + m) =
                    make_float2(acc[mf][nf][rh * 2 + 0], acc[mf][nf][rh * 2 + 1]);
            }
        }
    }
}

// =================================================================================
// softmax over last dim (256), in place on g_E
// =================================================================================
__global__ __launch_bounds__(256) void softmax_kernel()
{
    int warp = threadIdx.x >> 5, lane = threadIdx.x & 31;
    int row = blockIdx.x * 8 + warp;
    float* e = g_E + (size_t)row * NN;

    float4 a = ((float4*)e)[lane];
    float4 b = ((float4*)e)[lane + 32];
    float m = fmaxf(fmaxf(fmaxf(a.x, a.y), fmaxf(a.z, a.w)),
                    fmaxf(fmaxf(b.x, b.y), fmaxf(b.z, b.w)));
    #pragma unroll
    for (int off = 16; off; off >>= 1) m = fmaxf(m, __shfl_xor_sync(0xffffffffu, m, off));
    a.x = __expf(a.x - m); a.y = __expf(a.y - m); a.z = __expf(a.z - m); a.w = __expf(a.w - m);
    b.x = __expf(b.x - m); b.y = __expf(b.y - m); b.z = __expf(b.z - m); b.w = __expf(b.w - m);
    float s = a.x + a.y + a.z + a.w + b.x + b.y + b.z + b.w;
    #pragma unroll
    for (int off = 16; off; off >>= 1) s += __shfl_xor_sync(0xffffffffu, s, off);
    float inv = 1.0f / s;
    a.x *= inv; a.y *= inv; a.z *= inv; a.w *= inv;
    b.x *= inv; b.y *= inv; b.z *= inv; b.w *= inv;
    ((float4*)e)[lane] = a;
    ((float4*)e)[lane + 32] = b;
}

// =================================================================================
// AV (tf32 rna): Ot[n][c] = attn[n][:] . V[c][:]   (K = 256)
// =================================================================================
__global__ __launch_bounds__(256, 2) void av_mma()
{
    extern __shared__ float sm[];
    int hb = blockIdx.z;
    const float* A = g_E + (size_t)hb * NN * NN;
    const float* V = g_V + (size_t)hb * CH * NN;
    int rbase = blockIdx.y * 128;   // n
    int cbase = blockIdx.x * 128;   // c
    int tid = threadIdx.x;

    float acc[4][4][4] = {};
    run_gemm_tf<false>(acc, sm, A + (size_t)rbase * NN, NN,
                       V + (size_t)cbase * NN, NN, 8, nullptr, 0, tid);

    int wm = (tid >> 5) & 1, wn = tid >> 6, lr = (tid & 31) >> 2, lc = tid & 3;
    float* dst = g_Ot + (size_t)hb * NN * CH;
    #pragma unroll
    for (int mf = 0; mf < 4; mf++) {
        #pragma unroll
        for (int nf = 0; nf < 4; nf++) {
            int c = cbase + wn * 32 + nf * 8 + lc * 2;
            #pragma unroll
            for (int rh = 0; rh < 2; rh++) {
                int n = rbase + wm * 64 + mf * 16 + lr + rh * 8;
                *(float2*)(dst + (size_t)n * CH + c) =
                    make_float2(acc[mf][nf][rh * 2 + 0], acc[mf][nf][rh * 2 + 1]);
            }
        }
    }
}

// =================================================================================
// msw gating: one warp per (b, n)
// =================================================================================
__global__ __launch_bounds__(256) void msw_kernel(
    const float* __restrict__ mswW, const float* __restrict__ gg,
    const float* __restrict__ bbt,  const float* __restrict__ mmn,
    const float* __restrict__ vvr)
{
    int b = blockIdx.y;
    int n = blockIdx.x * 8 + (threadIdx.x >> 5);
    int lane = threadIdx.x & 31;
    float a0 = 0.f, a1 = 0.f, a2 = 0.f, a3 = 0.f;
    #pragma unroll
    for (int hd = 0; hd < NHEADS; hd++) {
        const float* base = g_Ot + ((size_t)(hd * BATCH + b) * NN + n) * CH;
        const float* w = mswW + hd * CH;
        for (int c = lane; c < CH; c += 32) {
            float xv = base[c];
            a0 += xv * w[c];
            a1 += xv * w[2560 + c];
            a2 += xv * w[2 * 2560 + c];
            a3 += xv * w[3 * 2560 + c];
        }
    }
    #pragma unroll
    for (int off = 16; off; off >>= 1) {
        a0 += __shfl_xor_sync(0xffffffffu, a0, off);
        a1 += __shfl_xor_sync(0xffffffffu, a1, off);
        a2 += __shfl_xor_sync(0xffffffffu, a2, off);
        a3 += __shfl_xor_sync(0xffffffffu, a3, off);
    }
    if (lane < 4) {
        float acc = lane == 0 ? a0 : lane == 1 ? a1 : lane == 2 ? a2 : a3;
        float z = (acc - mmn[lane]) * (gg[lane] * rsqrtf(vvr[lane] + BN_EPS)) + bbt[lane];
        g_WGT[(b * 4 + lane) * NN + n] = 1.f / (1.f + __expf(-z));
    }
}

// =================================================================================
// combine: x_ms[b][n][c] = Ot4 + sum_i w_i[n] * Ot_i
// =================================================================================
__global__ __launch_bounds__(256) void combine_kernel()
{
    int idx = blockIdx.x * 256 + threadIdx.x;
    int b = idx >> 17;
    int n = (idx >> 9) & 255;
    const float* w = g_WGT + b * 4 * NN;
    size_t hs = (size_t)BATCH * NN * CH;
    size_t off = (size_t)idx;
    float r = g_Ot[4 * hs + off]
            + w[n]          * g_Ot[off]
            + w[NN + n]     * g_Ot[hs + off]
            + w[2 * NN + n] * g_Ot[2 * hs + off]
            + w[3 * NN + n] * g_Ot[3 * hs + off];
    g_MS[off] = r;
}

// =================================================================================
// conv3x3 implicit GEMM (tf32 rna): D[o][n], K = 4608
// =================================================================================
__global__ __launch_bounds__(256, 2) void conv_mma()
{
    extern __shared__ float sm[];
    int b = blockIdx.z;
    int rbase = blockIdx.y * 128;   // o
    int cbase = blockIdx.x * 128;   // n
    const float* MSb = g_MS + (size_t)b * NN * CH;
    int tid = threadIdx.x;

    float acc[4][4][4] = {};
    run_gemm_tf<true>(acc, sm, g_Wp + (size_t)rbase * KCONV, KCONV,
                      nullptr, 0, 144, MSb, cbase, tid);

    int wm = (tid >> 5) & 1, wn = tid >> 6, lr = (tid & 31) >> 2, lc = tid & 3;
    float* dst = g_CV + (size_t)b * CH * NN;
    #pragma unroll
    for (int mf = 0; mf < 4; mf++) {
        #pragma unroll
        for (int nf = 0; nf < 4; nf++) {
            int n = cbase + wn * 32 + nf * 8 + lc * 2;
            #pragma unroll
            for (int rh = 0; rh < 2; rh++) {
                int o = rbase + wm * 64 + mf * 16 + lr + rh * 8;
                *(float2*)(dst + (size_t)o * NN + n) =
                    make_float2(acc[mf][nf][rh * 2 + 0], acc[mf][nf][rh * 2 + 1]);
            }
        }
    }
}

// =================================================================================
// final: out = relu(bn_top(relu(bn_fus(conv)) + x))
// =================================================================================
__global__ __launch_bounds__(256) void final_kernel(
    const float* __restrict__ x,
    const float* __restrict__ fg, const float* __restrict__ fb,
    const float* __restrict__ fm, const float* __restrict__ fv,
    const float* __restrict__ tg, const float* __restrict__ tb,
    const float* __restrict__ tm, const float* __restrict__ tv,
    float* __restrict__ out)
{
    int idx = blockIdx.x * 256 + threadIdx.x;
    int c = (idx >> 8) & 511;
    float t = g_CV[idx];
    t = (t - fm[c]) * (fg[c] * rsqrtf(fv[c] + BN_EPS)) + fb[c];
    t = fmaxf(t, 0.f);
    t += x[idx];
    t = (t - tm[c]) * (tg[c] * rsqrtf(tv[c] + BN_EPS)) + tb[c];
    out[idx] = fmaxf(t, 0.f);
}

// =================================================================================
extern "C" void kernel_launch(void* const* d_in, const int* in_sizes, int n_in,
                              void* d_out, int out_size)
{
    const float* x0   = (const float*)d_in[0];
    const float* x1   = (const float*)d_in[1];
    const float* x2   = (const float*)d_in[2];
    const float* x3   = (const float*)d_in[3];
    const float* x4   = (const float*)d_in[4];
    const float* qW   = (const float*)d_in[5];
    const float* qB   = (const float*)d_in[6];
    const float* kW   = (const float*)d_in[7];
    const float* kB   = (const float*)d_in[8];
    const float* vW   = (const float*)d_in[9];
    const float* vB   = (const float*)d_in[10];
    const float* relH = (const float*)d_in[11];
    const float* relW = (const float*)d_in[12];
    const float* mswW = (const float*)d_in[13];
    const float* mswg = (const float*)d_in[14];
    const float* mswb = (const float*)d_in[15];
    const float* mswm = (const float*)d_in[16];
    const float* mswv = (const float*)d_in[17];
    const float* fusW = (const float*)d_in[18];
    const float* fusg = (const float*)d_in[19];
    const float* fusb = (const float*)d_in[20];
    const float* fusm = (const float*)d_in[21];
    const float* fusv = (const float*)d_in[22];
    const float* topg = (const float*)d_in[23];
    const float* topb = (const float*)d_in[24];
    const float* topm = (const float*)d_in[25];
    const float* topv = (const float*)d_in[26];
    float* out = (float*)d_out;

    cudaFuncSetAttribute(qk_mma,     cudaFuncAttributeMaxDynamicSharedMemorySize, SMEMB_BYTES);
    cudaFuncSetAttribute(v_mma,      cudaFuncAttributeMaxDynamicSharedMemorySize, SMEMB_BYTES);
    cudaFuncSetAttribute(energy_mma, cudaFuncAttributeMaxDynamicSharedMemorySize, SMEMB_BYTES);
    cudaFuncSetAttribute(av_mma,     cudaFuncAttributeMaxDynamicSharedMemorySize, SMEM_BYTES);
    cudaFuncSetAttribute(conv_mma,   cudaFuncAttributeMaxDynamicSharedMemorySize, SMEM_BYTES);

    transpose_kernel<<<dim3(8, 16, NHEADS * BATCH), dim3(32, 8)>>>(x0, x1, x2, x3, x4);
    wsplit_kernel<<<dim3(NHEADS * CH * CH / 256, 1, 3), 256>>>(qW, kW, vW);
    permW_kernel<<<CH, 256>>>(fusW);

    // Q,K projections: D[n][o]
    qk_mma<<<dim3(4, 2, 2 * NHEADS * BATCH), 256, SMEMB_BYTES>>>(qB, kB, relH, relW);

    // V projection: D[o][m]
    v_mma<<<dim3(2, 4, NHEADS * BATCH), 256, SMEMB_BYTES>>>(vB);

    // energy: D[n][m]
    energy_mma<<<dim3(2, 2, NHEADS * BATCH), 256, SMEMB_BYTES>>>();

    softmax_kernel<<<(NHEADS * BATCH * NN) / 8, 256>>>();

    // AV: D[n][c]
    av_mma<<<dim3(4, 2, NHEADS * BATCH), 256, SMEM_BYTES>>>();

    msw_kernel<<<dim3(NN / 8, BATCH), 256>>>(mswW, mswg, mswb, mswm, mswv);
    combine_kernel<<<(BATCH * NN * CH) / 256, 256>>>();

    // conv: D[o][n]
    conv_mma<<<dim3(2, 4, BATCH), 256, SMEM_BYTES>>>();

    final_kernel<<<(BATCH * CH * NN) / 256, 256>>>(
        x4, fusg, fusb, fusm, fusv, topg, topb, topm, topv, out);
}